// round 1
// baseline (speedup 1.0000x reference)
#include <cuda_runtime.h>

#define NNODES 50000
#define EMB 64
#define INDIM 32
#define NACT 16

// ------------------------- scratch (static device globals; no allocs) ---------
__device__ float g_s0[NNODES * EMB];   // layer-0 scatter accumulator
__device__ float g_s1[NNODES * EMB];   // layer-1 scatter accumulator
__device__ float g_cnt[NNODES];        // per-node edge count (float)
__device__ float g_h[NNODES * EMB];    // node embedding after layer 0
__device__ float g_t[NNODES * EMB];    // inter-stage node temp
__device__ float g_hg[EMB];            // graph readout accumulator
__device__ float g_Wc[2][EMB * EMB];   // W2 @ We1[l]
__device__ float g_bc[2][EMB];         // b2 @ We1[l] + be1[l]

// ------------------------- packed f32x2 helpers -------------------------------
__device__ __forceinline__ unsigned long long fma2(unsigned long long a,
                                                   unsigned long long b,
                                                   unsigned long long c) {
    unsigned long long d;
    asm("fma.rn.f32x2 %0, %1, %2, %3;" : "=l"(d) : "l"(a), "l"(b), "l"(c));
    return d;
}
__device__ __forceinline__ unsigned long long dup2(float x) {
    unsigned long long d;
    asm("mov.b64 %0, {%1, %1};" : "=l"(d) : "f"(x));
    return d;
}
__device__ __forceinline__ unsigned long long pk2(float lo, float hi) {
    unsigned long long d;
    asm("mov.b64 %0, {%1, %2};" : "=l"(d) : "f"(lo), "f"(hi));
    return d;
}
__device__ __forceinline__ void up2(unsigned long long v, float& lo, float& hi) {
    asm("mov.b64 {%0, %1}, %2;" : "=f"(lo), "=f"(hi) : "l"(v));
}
__device__ __forceinline__ void red4(float* p, float a, float b, float c, float d) {
    asm volatile("red.global.add.v4.f32 [%0], {%1, %2, %3, %4};"
                 :: "l"(p), "f"(a), "f"(b), "f"(c), "f"(d) : "memory");
}
__device__ __forceinline__ void red1(float* p, float a) {
    asm volatile("red.global.add.f32 [%0], %1;" :: "l"(p), "f"(a) : "memory");
}

// y[64] = optional_relu( x[0..IN-1] @ W[IN][64] + bias*bscale )
// W in shared memory, read as ulonglong2 (LDS.128 broadcast -> 2 fma2 operands).
template <int IN, bool RELU>
__device__ __forceinline__ void mv64(const float* __restrict__ x,
                                     const ulonglong2* __restrict__ W,
                                     const float* __restrict__ bias, float bscale,
                                     float* __restrict__ y) {
    unsigned long long acc[32];
#pragma unroll
    for (int j = 0; j < 32; j++)
        acc[j] = pk2(bias[2 * j] * bscale, bias[2 * j + 1] * bscale);
#pragma unroll
    for (int k = 0; k < IN; k++) {
        unsigned long long x2 = dup2(x[k]);
#pragma unroll
        for (int j = 0; j < 16; j++) {
            ulonglong2 w = W[k * 16 + j];
            acc[2 * j]     = fma2(x2, w.x, acc[2 * j]);
            acc[2 * j + 1] = fma2(x2, w.y, acc[2 * j + 1]);
        }
    }
#pragma unroll
    for (int j = 0; j < 32; j++) {
        float lo, hi;
        up2(acc[j], lo, hi);
        if (RELU) { lo = fmaxf(lo, 0.f); hi = fmaxf(hi, 0.f); }
        y[2 * j] = lo;
        y[2 * j + 1] = hi;
    }
}

// ------------------------- kernels -------------------------------------------
__global__ void zero_kernel() {
    int i = blockIdx.x * blockDim.x + threadIdx.x;
    if (i < NNODES * EMB) { g_s0[i] = 0.f; g_s1[i] = 0.f; }
    if (i < NNODES) g_cnt[i] = 0.f;
    if (i < EMB) g_hg[i] = 0.f;
}

// g_Wc[l] = W2 @ We1[l];  g_bc[l] = b2 @ We1[l] + be1[l]
__global__ void prep_kernel(const float* __restrict__ W2, const float* __restrict__ b2,
                            const float* __restrict__ We1, const float* __restrict__ be1) {
    int idx = blockIdx.x * blockDim.x + threadIdx.x;
    if (idx < 2 * EMB * EMB) {
        int l = idx / (EMB * EMB);
        int r = idx % (EMB * EMB);
        int k = r / EMB, j = r % EMB;
        float a = 0.f;
        for (int i = 0; i < EMB; i++)
            a += W2[k * EMB + i] * We1[l * EMB * EMB + i * EMB + j];
        g_Wc[l][r] = a;
    } else if (idx < 2 * EMB * EMB + 2 * EMB) {
        int t2 = idx - 2 * EMB * EMB;
        int l = t2 / EMB, j = t2 % EMB;
        float a = be1[l * EMB + j];
        for (int i = 0; i < EMB; i++)
            a += b2[i] * We1[l * EMB * EMB + i * EMB + j];
        g_bc[l][j] = a;
    }
}

// One fused pass over all edges: t1 -> u0 -> scatter s0, u1 -> scatter s1, cnt.
__global__ void __launch_bounds__(128) edge_kernel(
    const float* __restrict__ obs, const int* __restrict__ dst,
    const float* __restrict__ W1, const float* __restrict__ b1, int E) {
    __shared__ __align__(16) float sW1[INDIM * EMB];
    __shared__ __align__(16) float sWc0[EMB * EMB];
    __shared__ __align__(16) float sWc1[EMB * EMB];
    for (int i = threadIdx.x; i < INDIM * EMB; i += 128) sW1[i] = W1[i];
    for (int i = threadIdx.x; i < EMB * EMB; i += 128) {
        sWc0[i] = g_Wc[0][i];
        sWc1[i] = g_Wc[1][i];
    }
    __syncthreads();

    int e = blockIdx.x * 128 + threadIdx.x;
    if (e >= E) return;

    float x[INDIM];
    const float4* o4 = reinterpret_cast<const float4*>(obs + (size_t)e * INDIM);
#pragma unroll
    for (int i = 0; i < INDIM / 4; i++) {
        float4 v = o4[i];
        x[4 * i] = v.x; x[4 * i + 1] = v.y; x[4 * i + 2] = v.z; x[4 * i + 3] = v.w;
    }

    float t1[EMB];
    mv64<INDIM, true>(x, (const ulonglong2*)sW1, b1, 1.0f, t1);

    int d = dst[e];
#pragma unroll 1
    for (int s = 0; s < 2; s++) {
        const ulonglong2* W = s ? (const ulonglong2*)sWc1 : (const ulonglong2*)sWc0;
        float u[EMB];
        mv64<EMB, true>(t1, W, g_bc[s], 1.0f, u);
        float* p = (s ? g_s1 : g_s0) + (size_t)d * EMB;
#pragma unroll
        for (int j = 0; j < 16; j++)
            red4(p + 4 * j, u[4 * j], u[4 * j + 1], u[4 * j + 2], u[4 * j + 3]);
    }
    red1(&g_cnt[d], 1.0f);
}

// agg = h^(l) * (s @ We2 + cnt*be2);  t = relu(agg @ Wn3 + bn3)
__global__ void __launch_bounds__(128) node_a_kernel(
    const float* __restrict__ We2l, const float* __restrict__ be2l,
    const float* __restrict__ Wn3l, const float* __restrict__ bn3l, int layer) {
    __shared__ __align__(16) float sWe2[EMB * EMB];
    __shared__ __align__(16) float sWn3[EMB * EMB];
    for (int i = threadIdx.x; i < EMB * EMB; i += 128) {
        sWe2[i] = We2l[i];
        sWn3[i] = Wn3l[i];
    }
    __syncthreads();

    int v = blockIdx.x * 128 + threadIdx.x;
    if (v >= NNODES) return;

    const float* sp = (layer == 0) ? (g_s0 + (size_t)v * EMB) : (g_s1 + (size_t)v * EMB);
    float sv[EMB];
    const float4* s4 = (const float4*)sp;
#pragma unroll
    for (int i = 0; i < 16; i++) {
        float4 q = s4[i];
        sv[4 * i] = q.x; sv[4 * i + 1] = q.y; sv[4 * i + 2] = q.z; sv[4 * i + 3] = q.w;
    }
    float cnt = g_cnt[v];

    float agg[EMB];
    mv64<EMB, false>(sv, (const ulonglong2*)sWe2, be2l, cnt, agg);

    if (layer == 1) {
        const float4* h4 = (const float4*)(g_h + (size_t)v * EMB);
#pragma unroll
        for (int i = 0; i < 16; i++) {
            float4 hv = h4[i];
            agg[4 * i] *= hv.x; agg[4 * i + 1] *= hv.y;
            agg[4 * i + 2] *= hv.z; agg[4 * i + 3] *= hv.w;
        }
    }

    float t[EMB];
    mv64<EMB, true>(agg, (const ulonglong2*)sWn3, bn3l, 1.0f, t);

    float4* t4 = (float4*)(g_t + (size_t)v * EMB);
#pragma unroll
    for (int i = 0; i < 16; i++)
        t4[i] = make_float4(t[4 * i], t[4 * i + 1], t[4 * i + 2], t[4 * i + 3]);
}

// hn = relu(t @ Wn4 + bn4); layer0 -> write g_h; layer1 -> reduce into g_hg
__global__ void __launch_bounds__(128) node_b_kernel(
    const float* __restrict__ Wn4l, const float* __restrict__ bn4l, int layer) {
    __shared__ __align__(16) float sWn4[EMB * EMB];
    for (int i = threadIdx.x; i < EMB * EMB; i += 128) sWn4[i] = Wn4l[i];
    __syncthreads();

    int v = blockIdx.x * 128 + threadIdx.x;
    bool active = (v < NNODES);
    float hn[EMB];
    if (active) {
        float t[EMB];
        const float4* t4 = (const float4*)(g_t + (size_t)v * EMB);
#pragma unroll
        for (int i = 0; i < 16; i++) {
            float4 q = t4[i];
            t[4 * i] = q.x; t[4 * i + 1] = q.y; t[4 * i + 2] = q.z; t[4 * i + 3] = q.w;
        }
        mv64<EMB, false>(t, (const ulonglong2*)sWn4, bn4l, 1.0f, hn);
#pragma unroll
        for (int j = 0; j < EMB; j++) hn[j] = fmaxf(hn[j], 0.f);
        if (layer == 0) {
            float4* h4 = (float4*)(g_h + (size_t)v * EMB);
#pragma unroll
            for (int i = 0; i < 16; i++)
                h4[i] = make_float4(hn[4 * i], hn[4 * i + 1], hn[4 * i + 2], hn[4 * i + 3]);
        }
    } else {
#pragma unroll
        for (int j = 0; j < EMB; j++) hn[j] = 0.f;
    }

    if (layer == 1) {
#pragma unroll
        for (int j = 0; j < EMB; j++) {
            float s = hn[j];
            s += __shfl_xor_sync(0xffffffffu, s, 16);
            s += __shfl_xor_sync(0xffffffffu, s, 8);
            s += __shfl_xor_sync(0xffffffffu, s, 4);
            s += __shfl_xor_sync(0xffffffffu, s, 2);
            s += __shfl_xor_sync(0xffffffffu, s, 1);
            hn[j] = s;
        }
        if ((threadIdx.x & 31) == 0) {
#pragma unroll
            for (int j = 0; j < 16; j++)
                red4(g_hg + 4 * j, hn[4 * j], hn[4 * j + 1], hn[4 * j + 2], hn[4 * j + 3]);
        }
    }
}

// hg -> relu(hg@W3+b3) @ W4 + b4  -> out[16]
__global__ void final_kernel(const float* __restrict__ W3, const float* __restrict__ b3,
                             const float* __restrict__ W4, const float* __restrict__ b4,
                             float* __restrict__ out) {
    __shared__ float sh[EMB];
    int j = threadIdx.x;  // 64 threads
    float a = b3[j];
#pragma unroll
    for (int k = 0; k < EMB; k++) a += g_hg[k] * W3[k * EMB + j];
    sh[j] = fmaxf(a, 0.f);
    __syncthreads();
    if (j < NACT) {
        float o = b4[j];
#pragma unroll
        for (int k = 0; k < EMB; k++) o += sh[k] * W4[k * NACT + j];
        out[j] = o;
    }
}

// ------------------------- launch --------------------------------------------
extern "C" void kernel_launch(void* const* d_in, const int* in_sizes, int n_in,
                              void* d_out, int out_size) {
    const float* edge_obs = (const float*)d_in[0];
    const int* dst = (const int*)d_in[1];
    // n_nodes may appear as a 1-element int input at index 2; skip it if present.
    int o = (n_in >= 19 && in_sizes[2] == 1) ? 3 : 2;
    const float* W1  = (const float*)d_in[o + 0];
    const float* b1  = (const float*)d_in[o + 1];
    const float* W2  = (const float*)d_in[o + 2];
    const float* b2  = (const float*)d_in[o + 3];
    const float* We1 = (const float*)d_in[o + 4];
    const float* be1 = (const float*)d_in[o + 5];
    const float* We2 = (const float*)d_in[o + 6];
    const float* be2 = (const float*)d_in[o + 7];
    const float* Wn3 = (const float*)d_in[o + 8];
    const float* bn3 = (const float*)d_in[o + 9];
    const float* Wn4 = (const float*)d_in[o + 10];
    const float* bn4 = (const float*)d_in[o + 11];
    const float* W3  = (const float*)d_in[o + 12];
    const float* b3  = (const float*)d_in[o + 13];
    const float* W4  = (const float*)d_in[o + 14];
    const float* b4  = (const float*)d_in[o + 15];
    float* out = (float*)d_out;
    int E = in_sizes[0] / INDIM;

    zero_kernel<<<(NNODES * EMB + 255) / 256, 256>>>();
    prep_kernel<<<(2 * EMB * EMB + 2 * EMB + 127) / 128, 128>>>(W2, b2, We1, be1);
    edge_kernel<<<(E + 127) / 128, 128>>>(edge_obs, dst, W1, b1, E);
    for (int l = 0; l < 2; l++) {
        node_a_kernel<<<(NNODES + 127) / 128, 128>>>(
            We2 + l * EMB * EMB, be2 + l * EMB, Wn3 + l * EMB * EMB, bn3 + l * EMB, l);
        node_b_kernel<<<(NNODES + 127) / 128, 128>>>(Wn4 + l * EMB * EMB, bn4 + l * EMB, l);
    }
    final_kernel<<<1, EMB>>>(W3, b3, W4, b4, out);
}

// round 2
// speedup vs baseline: 2.0281x; 2.0281x over previous
#include <cuda_runtime.h>

#define NNODES 50000
#define EMB 64
#define INDIM 32
#define NACT 16

typedef unsigned long long u64;

// ------------------------- scratch (static device globals) --------------------
__device__ float g_s0[NNODES * EMB];   // layer-0 scatter accumulator
__device__ float g_s1[NNODES * EMB];   // layer-1 scatter accumulator
__device__ float g_cnt[NNODES];        // per-node edge count
__device__ float g_h[NNODES * EMB];    // node embedding after layer 0
__device__ float g_hg[EMB];            // graph readout accumulator
__device__ float g_Wc[2][EMB * EMB];   // W2 @ We1[l]
__device__ float g_bc[2][EMB];         // b2 @ We1[l] + be1[l]

// ------------------------- packed f32x2 helpers -------------------------------
__device__ __forceinline__ u64 fma2(u64 a, u64 b, u64 c) {
    u64 d;
    asm("fma.rn.f32x2 %0, %1, %2, %3;" : "=l"(d) : "l"(a), "l"(b), "l"(c));
    return d;
}
__device__ __forceinline__ u64 mul2(u64 a, u64 b) {
    u64 d;
    asm("mul.rn.f32x2 %0, %1, %2;" : "=l"(d) : "l"(a), "l"(b));
    return d;
}
__device__ __forceinline__ u64 dup2(float x) {
    u64 d;
    asm("mov.b64 %0, {%1, %1};" : "=l"(d) : "f"(x));
    return d;
}
__device__ __forceinline__ u64 pk2(float lo, float hi) {
    u64 d;
    asm("mov.b64 %0, {%1, %2};" : "=l"(d) : "f"(lo), "f"(hi));
    return d;
}
__device__ __forceinline__ void up2(u64 v, float& lo, float& hi) {
    asm("mov.b64 {%0, %1}, %2;" : "=f"(lo), "=f"(hi) : "l"(v));
}
__device__ __forceinline__ void red4(float* p, float a, float b, float c, float d) {
    asm volatile("red.global.add.v4.f32 [%0], {%1, %2, %3, %4};"
                 :: "l"(p), "f"(a), "f"(b), "f"(c), "f"(d) : "memory");
}
__device__ __forceinline__ void red1(float* p, float a) {
    asm volatile("red.global.add.f32 [%0], %1;" :: "l"(p), "f"(a) : "memory");
}

// XOR-swizzled [row][128-col] smem addressing (conflict-free transpose)
__device__ __forceinline__ int swz(int row, int col) {
    return row * 128 + (col ^ ((((row) >> 3) & 7) << 2));
}

// ------------------------- tiled GEMM core ------------------------------------
// acc[4][4] covers [4 rows e0..e0+3] x [8 outs j0..j0+7 packed as 4 f32x2].
// sIn: swizzled [KDIM][128]; sW: plain [KDIM][64] k-major.
template <int KDIM>
__device__ __forceinline__ void gemm_tile(const float* __restrict__ sIn,
                                          const float* __restrict__ sW,
                                          u64 acc[4][4], int e0, int j0) {
#pragma unroll
    for (int k = 0; k < KDIM; k++) {
        float4 xv = *(const float4*)&sIn[swz(k, e0)];
        ulonglong2 wa = *(const ulonglong2*)&sW[k * 64 + j0];
        ulonglong2 wb = *(const ulonglong2*)&sW[k * 64 + j0 + 4];
        u64 xs;
        xs = dup2(xv.x);
        acc[0][0] = fma2(xs, wa.x, acc[0][0]); acc[0][1] = fma2(xs, wa.y, acc[0][1]);
        acc[0][2] = fma2(xs, wb.x, acc[0][2]); acc[0][3] = fma2(xs, wb.y, acc[0][3]);
        xs = dup2(xv.y);
        acc[1][0] = fma2(xs, wa.x, acc[1][0]); acc[1][1] = fma2(xs, wa.y, acc[1][1]);
        acc[1][2] = fma2(xs, wb.x, acc[1][2]); acc[1][3] = fma2(xs, wb.y, acc[1][3]);
        xs = dup2(xv.z);
        acc[2][0] = fma2(xs, wa.x, acc[2][0]); acc[2][1] = fma2(xs, wa.y, acc[2][1]);
        acc[2][2] = fma2(xs, wb.x, acc[2][2]); acc[2][3] = fma2(xs, wb.y, acc[2][3]);
        xs = dup2(xv.w);
        acc[3][0] = fma2(xs, wa.x, acc[3][0]); acc[3][1] = fma2(xs, wa.y, acc[3][1]);
        acc[3][2] = fma2(xs, wb.x, acc[3][2]); acc[3][3] = fma2(xs, wb.y, acc[3][3]);
    }
}

__device__ __forceinline__ void unpack4(const u64 a[4][4], float tv[4][8], bool dorelu) {
#pragma unroll
    for (int ee = 0; ee < 4; ++ee)
#pragma unroll
        for (int jj = 0; jj < 4; ++jj) {
            float lo, hi;
            up2(a[ee][jj], lo, hi);
            if (dorelu) { lo = fmaxf(lo, 0.f); hi = fmaxf(hi, 0.f); }
            tv[ee][2 * jj] = lo;
            tv[ee][2 * jj + 1] = hi;
        }
}

// transposed (out-major, swizzled) store of a thread micro-tile
__device__ __forceinline__ void store_tile_T(float* sOut, const float tv[4][8],
                                             int e0, int j0) {
#pragma unroll
    for (int jd = 0; jd < 8; ++jd) {
        int j = j0 + jd;
        *(float4*)&sOut[swz(j, e0)] =
            make_float4(tv[0][jd], tv[1][jd], tv[2][jd], tv[3][jd]);
    }
}

// ------------------------- small kernels --------------------------------------
__global__ void zero_kernel() {
    int i = blockIdx.x * blockDim.x + threadIdx.x;
    if (i < NNODES * EMB) { g_s0[i] = 0.f; g_s1[i] = 0.f; }
    if (i < NNODES) g_cnt[i] = 0.f;
    if (i < EMB) g_hg[i] = 0.f;
}

__global__ void prep_kernel(const float* __restrict__ W2, const float* __restrict__ b2,
                            const float* __restrict__ We1, const float* __restrict__ be1) {
    int idx = blockIdx.x * blockDim.x + threadIdx.x;
    if (idx < 2 * EMB * EMB) {
        int l = idx / (EMB * EMB);
        int r = idx % (EMB * EMB);
        int k = r / EMB, j = r % EMB;
        float a = 0.f;
        for (int i = 0; i < EMB; i++)
            a += W2[k * EMB + i] * We1[l * EMB * EMB + i * EMB + j];
        g_Wc[l][r] = a;
    } else if (idx < 2 * EMB * EMB + 2 * EMB) {
        int t2 = idx - 2 * EMB * EMB;
        int l = t2 / EMB, j = t2 % EMB;
        float a = be1[l * EMB + j];
        for (int i = 0; i < EMB; i++)
            a += b2[i] * We1[l * EMB * EMB + i * EMB + j];
        g_bc[l][j] = a;
    }
}

// ------------------------- edge kernel ----------------------------------------
// smem layout (floats):
//   sX   [32][128] swizzled           4096
//   sT   [64][128] swizzled           8192
//   sW1  [32][64]                     2048
//   sWc0 [64][64]                     4096
//   sWc1 [64][64]                     4096
//   sB1  [64]                           64
//   sBc  [128]                         128
//   sDst [128] (int)                   128
#define EDGE_SMEM_FLOATS (4096 + 8192 + 2048 + 4096 + 4096 + 64 + 128 + 128)

__global__ void __launch_bounds__(256, 2) edge_kernel(
    const float* __restrict__ obs, const int* __restrict__ dst,
    const float* __restrict__ W1, const float* __restrict__ b1, int E) {
    extern __shared__ float sm[];
    float* sX = sm;
    float* sT = sX + 4096;
    float* sW1 = sT + 8192;
    float* sWc0 = sW1 + 2048;
    float* sWc1 = sWc0 + 4096;
    float* sB1 = sWc1 + 4096;
    float* sBc = sB1 + 64;
    int* sDst = (int*)(sBc + 128);

    int t = threadIdx.x;
    int base = blockIdx.x * 128;

    // weight loads
    {
        const float4* src = (const float4*)W1;
        float4* d4 = (float4*)sW1;
        d4[t] = src[t];
        d4[t + 256] = src[t + 256];
    }
    {
        const float4* src = (const float4*)&g_Wc[0][0];
        float4* d4 = (float4*)sWc0;  // sWc0 and sWc1 contiguous
#pragma unroll
        for (int i = 0; i < 8; i++) d4[t + 256 * i] = src[t + 256 * i];
    }
    if (t < 64) sB1[t] = b1[t];
    if (t < 128) sBc[t] = (&g_bc[0][0])[t];
    if (t < 128) {
        int e = base + t;
        sDst[t] = (e < E) ? dst[e] : -1;
    }
    // obs tile, transposed into swizzled sX
#pragma unroll
    for (int it = 0; it < 4; ++it) {
        int idx = t + 256 * it;       // 0..1023
        int e = idx >> 3;             // 0..127
        int q = idx & 7;              // float4 within row of 32
        int ge = base + e;
        float4 v = (ge < E) ? ((const float4*)obs)[(size_t)ge * 8 + q]
                            : make_float4(0.f, 0.f, 0.f, 0.f);
        sX[swz(q * 4 + 0, e)] = v.x;
        sX[swz(q * 4 + 1, e)] = v.y;
        sX[swz(q * 4 + 2, e)] = v.z;
        sX[swz(q * 4 + 3, e)] = v.w;
    }
    __syncthreads();

    int tx = t & 7, te = t >> 3;
    int e0 = te * 4, j0 = tx * 8;

    // ---- GEMM1: t1 = relu(X @ W1 + b1) ----
    u64 acc[4][4];
    {
        u64 bz[4];
#pragma unroll
        for (int jj = 0; jj < 4; jj++)
            bz[jj] = pk2(sB1[j0 + 2 * jj], sB1[j0 + 2 * jj + 1]);
#pragma unroll
        for (int ee = 0; ee < 4; ee++)
#pragma unroll
            for (int jj = 0; jj < 4; jj++) acc[ee][jj] = bz[jj];
    }
    gemm_tile<32>(sX, sW1, acc, e0, j0);
    {
        float tv[4][8];
        unpack4(acc, tv, true);
        store_tile_T(sT, tv, e0, j0);
    }
    __syncthreads();

    // ---- GEMM2 (layer s), then scatter ----
#pragma unroll 1
    for (int s = 0; s < 2; s++) {
        const float* sW = s ? sWc1 : sWc0;
        const float* bc = sBc + s * 64;
        float* gS = s ? g_s1 : g_s0;
        u64 a[4][4];
        {
            u64 bz[4];
#pragma unroll
            for (int jj = 0; jj < 4; jj++)
                bz[jj] = pk2(bc[j0 + 2 * jj], bc[j0 + 2 * jj + 1]);
#pragma unroll
            for (int ee = 0; ee < 4; ee++)
#pragma unroll
                for (int jj = 0; jj < 4; jj++) a[ee][jj] = bz[jj];
        }
        gemm_tile<64>(sT, sW, a, e0, j0);
        float tv[4][8];
        unpack4(a, tv, true);
#pragma unroll
        for (int ee = 0; ee < 4; ee++) {
            int d = sDst[e0 + ee];
            if (d >= 0) {
                float* p = gS + (size_t)d * 64 + j0;
                red4(p, tv[ee][0], tv[ee][1], tv[ee][2], tv[ee][3]);
                red4(p + 4, tv[ee][4], tv[ee][5], tv[ee][6], tv[ee][7]);
            }
        }
    }
    if (tx == 0) {
#pragma unroll
        for (int ee = 0; ee < 4; ee++) {
            int d = sDst[e0 + ee];
            if (d >= 0) red1(&g_cnt[d], 1.f);
        }
    }
}

// ------------------------- fused node kernel ----------------------------------
// smem: sA [64][128] 8192, sB [64][128] 8192, sW [64][64] 4096,
//       sBias[192], sCnt[128]
#define NODE_SMEM_FLOATS (8192 + 8192 + 4096 + 192 + 128)

__global__ void __launch_bounds__(256, 2) node_kernel(
    const float* __restrict__ We2l, const float* __restrict__ be2l,
    const float* __restrict__ Wn3l, const float* __restrict__ bn3l,
    const float* __restrict__ Wn4l, const float* __restrict__ bn4l, int layer) {
    extern __shared__ float sm[];
    float* sA = sm;
    float* sB = sA + 8192;
    float* sW = sB + 8192;
    float* sBias = sW + 4096;
    float* sCnt = sBias + 192;

    int t = threadIdx.x;
    int base = blockIdx.x * 128;
    const float* gS = (layer == 0) ? g_s0 : g_s1;

    // load s-tile transposed into swizzled sA
#pragma unroll
    for (int it = 0; it < 8; ++it) {
        int idx = t + 256 * it;      // 0..2047
        int v = idx & 127;
        int q = idx >> 7;            // 0..15
        int gv = base + v;
        float4 x = (gv < NNODES) ? ((const float4*)gS)[(size_t)gv * 16 + q]
                                 : make_float4(0.f, 0.f, 0.f, 0.f);
        sA[swz(q * 4 + 0, v)] = x.x;
        sA[swz(q * 4 + 1, v)] = x.y;
        sA[swz(q * 4 + 2, v)] = x.z;
        sA[swz(q * 4 + 3, v)] = x.w;
    }
    if (t < 128) {
        int gv = base + t;
        sCnt[t] = (gv < NNODES) ? g_cnt[gv] : 0.f;
    }
    if (t < 64) {
        sBias[t] = be2l[t];
        sBias[64 + t] = bn3l[t];
        sBias[128 + t] = bn4l[t];
    }
    {
        float4* d4 = (float4*)sW;
        const float4* s4 = (const float4*)We2l;
#pragma unroll
        for (int i = 0; i < 4; i++) d4[t + 256 * i] = s4[t + 256 * i];
    }
    __syncthreads();

    int tx = t & 7, te = t >> 3;
    int e0 = te * 4, j0 = tx * 8;

    // ---- stage A: agg = s @ We2 + cnt*be2 (then *h for layer 1) ----
    u64 a[4][4];
    {
        u64 bp[4];
#pragma unroll
        for (int jj = 0; jj < 4; jj++)
            bp[jj] = pk2(sBias[j0 + 2 * jj], sBias[j0 + 2 * jj + 1]);
#pragma unroll
        for (int ee = 0; ee < 4; ee++) {
            u64 c = dup2(sCnt[e0 + ee]);
#pragma unroll
            for (int jj = 0; jj < 4; jj++) a[ee][jj] = mul2(c, bp[jj]);
        }
    }
    gemm_tile<64>(sA, sW, a, e0, j0);
    __syncthreads();  // reads of sA & sW done

    {
        float tv[4][8];
        unpack4(a, tv, false);
        if (layer == 1) {
#pragma unroll
            for (int ee = 0; ee < 4; ee++) {
                int gv = base + e0 + ee;
                if (gv < NNODES) {
                    float4 h1 = ((const float4*)g_h)[(size_t)gv * 16 + (j0 >> 2)];
                    float4 h2 = ((const float4*)g_h)[(size_t)gv * 16 + (j0 >> 2) + 1];
                    tv[ee][0] *= h1.x; tv[ee][1] *= h1.y;
                    tv[ee][2] *= h1.z; tv[ee][3] *= h1.w;
                    tv[ee][4] *= h2.x; tv[ee][5] *= h2.y;
                    tv[ee][6] *= h2.z; tv[ee][7] *= h2.w;
                }
            }
        }
        store_tile_T(sB, tv, e0, j0);
    }
    {
        float4* d4 = (float4*)sW;
        const float4* s4 = (const float4*)Wn3l;
#pragma unroll
        for (int i = 0; i < 4; i++) d4[t + 256 * i] = s4[t + 256 * i];
    }
    __syncthreads();

    // ---- stage B: tB = relu(agg @ Wn3 + bn3) ----
    u64 b[4][4];
    {
        u64 bp[4];
#pragma unroll
        for (int jj = 0; jj < 4; jj++)
            bp[jj] = pk2(sBias[64 + j0 + 2 * jj], sBias[64 + j0 + 2 * jj + 1]);
#pragma unroll
        for (int ee = 0; ee < 4; ee++)
#pragma unroll
            for (int jj = 0; jj < 4; jj++) b[ee][jj] = bp[jj];
    }
    gemm_tile<64>(sB, sW, b, e0, j0);
    __syncthreads();
    {
        float tv[4][8];
        unpack4(b, tv, true);
        store_tile_T(sA, tv, e0, j0);
    }
    {
        float4* d4 = (float4*)sW;
        const float4* s4 = (const float4*)Wn4l;
#pragma unroll
        for (int i = 0; i < 4; i++) d4[t + 256 * i] = s4[t + 256 * i];
    }
    __syncthreads();

    // ---- stage C: hn = relu(tB @ Wn4 + bn4) ----
    u64 c[4][4];
    {
        u64 bp[4];
#pragma unroll
        for (int jj = 0; jj < 4; jj++)
            bp[jj] = pk2(sBias[128 + j0 + 2 * jj], sBias[128 + j0 + 2 * jj + 1]);
#pragma unroll
        for (int ee = 0; ee < 4; ee++)
#pragma unroll
            for (int jj = 0; jj < 4; jj++) c[ee][jj] = bp[jj];
    }
    gemm_tile<64>(sA, sW, c, e0, j0);
    float hv[4][8];
    unpack4(c, hv, true);

    if (layer == 0) {
#pragma unroll
        for (int ee = 0; ee < 4; ee++) {
            int gv = base + e0 + ee;
            if (gv < NNODES) {
                float4* d4 = (float4*)(g_h + (size_t)gv * 64 + j0);
                d4[0] = make_float4(hv[ee][0], hv[ee][1], hv[ee][2], hv[ee][3]);
                d4[1] = make_float4(hv[ee][4], hv[ee][5], hv[ee][6], hv[ee][7]);
            }
        }
    } else {
        float p[8];
#pragma unroll
        for (int jd = 0; jd < 8; jd++) p[jd] = 0.f;
#pragma unroll
        for (int ee = 0; ee < 4; ee++) {
            int gv = base + e0 + ee;
            if (gv < NNODES) {
#pragma unroll
                for (int jd = 0; jd < 8; jd++) p[jd] += hv[ee][jd];
            }
        }
        __syncthreads();  // sA reads done; reuse as reduction scratch
        float* sRed = sA;  // [32 te][64 j]
        *(float4*)&sRed[te * 64 + j0] = make_float4(p[0], p[1], p[2], p[3]);
        *(float4*)&sRed[te * 64 + j0 + 4] = make_float4(p[4], p[5], p[6], p[7]);
        __syncthreads();
        if (t < 64) {
            float s = 0.f;
#pragma unroll
            for (int r = 0; r < 32; r++) s += sRed[r * 64 + t];
            red1(&g_hg[t], s);
        }
    }
}

// ------------------------- readout --------------------------------------------
__global__ void final_kernel(const float* __restrict__ W3, const float* __restrict__ b3,
                             const float* __restrict__ W4, const float* __restrict__ b4,
                             float* __restrict__ out) {
    __shared__ float sh[EMB];
    int j = threadIdx.x;  // 64 threads
    float a = b3[j];
#pragma unroll
    for (int k = 0; k < EMB; k++) a += g_hg[k] * W3[k * EMB + j];
    sh[j] = fmaxf(a, 0.f);
    __syncthreads();
    if (j < NACT) {
        float o = b4[j];
#pragma unroll
        for (int k = 0; k < EMB; k++) o += sh[k] * W4[k * NACT + j];
        out[j] = o;
    }
}

// ------------------------- launch ---------------------------------------------
extern "C" void kernel_launch(void* const* d_in, const int* in_sizes, int n_in,
                              void* d_out, int out_size) {
    const float* edge_obs = (const float*)d_in[0];
    const int* dst = (const int*)d_in[1];
    int o = (n_in >= 19 && in_sizes[2] == 1) ? 3 : 2;
    const float* W1  = (const float*)d_in[o + 0];
    const float* b1  = (const float*)d_in[o + 1];
    const float* W2  = (const float*)d_in[o + 2];
    const float* b2  = (const float*)d_in[o + 3];
    const float* We1 = (const float*)d_in[o + 4];
    const float* be1 = (const float*)d_in[o + 5];
    const float* We2 = (const float*)d_in[o + 6];
    const float* be2 = (const float*)d_in[o + 7];
    const float* Wn3 = (const float*)d_in[o + 8];
    const float* bn3 = (const float*)d_in[o + 9];
    const float* Wn4 = (const float*)d_in[o + 10];
    const float* bn4 = (const float*)d_in[o + 11];
    const float* W3  = (const float*)d_in[o + 12];
    const float* b3  = (const float*)d_in[o + 13];
    const float* W4  = (const float*)d_in[o + 14];
    const float* b4  = (const float*)d_in[o + 15];
    float* out = (float*)d_out;
    int E = in_sizes[0] / INDIM;

    static bool attr_done = false;
    cudaFuncSetAttribute(edge_kernel, cudaFuncAttributeMaxDynamicSharedMemorySize,
                         EDGE_SMEM_FLOATS * 4);
    cudaFuncSetAttribute(node_kernel, cudaFuncAttributeMaxDynamicSharedMemorySize,
                         NODE_SMEM_FLOATS * 4);
    (void)attr_done;

    zero_kernel<<<(NNODES * EMB + 255) / 256, 256>>>();
    prep_kernel<<<(2 * EMB * EMB + 2 * EMB + 127) / 128, 128>>>(W2, b2, We1, be1);
    edge_kernel<<<(E + 127) / 128, 256, EDGE_SMEM_FLOATS * 4>>>(edge_obs, dst, W1, b1, E);
    for (int l = 0; l < 2; l++) {
        node_kernel<<<(NNODES + 127) / 128, 256, NODE_SMEM_FLOATS * 4>>>(
            We2 + l * EMB * EMB, be2 + l * EMB,
            Wn3 + l * EMB * EMB, bn3 + l * EMB,
            Wn4 + l * EMB * EMB, bn4 + l * EMB, l);
    }
    final_kernel<<<1, EMB>>>(W3, b3, W4, b4, out);
}

// round 4
// speedup vs baseline: 2.9463x; 1.4527x over previous
#include <cuda_runtime.h>

#define NNODES 50000
#define EMB 64
#define INDIM 32
#define NACT 16

typedef unsigned long long u64;

// ------------------------- scratch (static device globals) --------------------
__device__ float g_s0[NNODES * EMB];
__device__ float g_s1[NNODES * EMB];
__device__ float g_cnt[NNODES];
__device__ float g_h[NNODES * EMB];
__device__ float g_hg[EMB];
__device__ float g_Wc[2][EMB * EMB];
__device__ float g_bc[2][EMB];

// ------------------------- packed f32x2 helpers -------------------------------
__device__ __forceinline__ u64 fma2(u64 a, u64 b, u64 c) {
    u64 d;
    asm("fma.rn.f32x2 %0, %1, %2, %3;" : "=l"(d) : "l"(a), "l"(b), "l"(c));
    return d;
}
__device__ __forceinline__ u64 mul2(u64 a, u64 b) {
    u64 d;
    asm("mul.rn.f32x2 %0, %1, %2;" : "=l"(d) : "l"(a), "l"(b));
    return d;
}
__device__ __forceinline__ u64 dup2(float x) {
    u64 d;
    asm("mov.b64 %0, {%1, %1};" : "=l"(d) : "f"(x));
    return d;
}
__device__ __forceinline__ u64 pk2(float lo, float hi) {
    u64 d;
    asm("mov.b64 %0, {%1, %2};" : "=l"(d) : "f"(lo), "f"(hi));
    return d;
}
__device__ __forceinline__ void up2(u64 v, float& lo, float& hi) {
    asm("mov.b64 {%0, %1}, %2;" : "=f"(lo), "=f"(hi) : "l"(v));
}
__device__ __forceinline__ void red4(float* p, float a, float b, float c, float d) {
    asm volatile("red.global.add.v4.f32 [%0], {%1, %2, %3, %4};"
                 :: "l"(p), "f"(a), "f"(b), "f"(c), "f"(d) : "memory");
}
__device__ __forceinline__ void red1(float* p, float a) {
    asm volatile("red.global.add.f32 [%0], %1;" :: "l"(p), "f"(a) : "memory");
}

// XOR-swizzled [row][128-col] smem addressing (conflict-free transpose)
__device__ __forceinline__ int swz(int row, int col) {
    return row * 128 + (col ^ ((((row) >> 3) & 7) << 2));
}

// Load a [rows x 64] weight matrix into smem with within-row chunk permutation:
// original 16B chunk c = j>>2 goes to byte offset (c&1)*128 + (c>>1)*16.
// Then thread tx reads its 8 outputs j0=tx*8 as two conflict-free LDS.128:
//   wa (j0..j0+3)  at  k*256B + tx*16B        (contiguous 128B across tx)
//   wb (j0+4..j0+7) at k*256B + 128B + tx*16B
__device__ __forceinline__ void load_w_reordered(float* sW, const float* gW,
                                                 int n, int t, int nthr) {
    for (int idx = t; idx < n; idx += nthr) {
        int k = idx >> 6, j = idx & 63;
        int off = (k << 6) + ((j & 4) << 3) + ((j >> 3) << 2) + (j & 3);
        sW[off] = gW[idx];
    }
}

// ------------------------- tiled GEMM core (8 rows x 8 outs / thread) ---------
// acc[8][4]: 8 rows (e0..e0+7) x 8 outs (j0..j0+7) packed as 4 f32x2.
// sIn: swizzled [KDIM][128]; sW: reordered [KDIM][64].
template <int KDIM, int UNR>
__device__ __forceinline__ void gemm_tile8(const float* __restrict__ sIn,
                                           const float* __restrict__ sW,
                                           u64 acc[8][4], int e0, int tx) {
#pragma unroll UNR
    for (int k = 0; k < KDIM; k++) {
        float4 xa = *(const float4*)&sIn[swz(k, e0)];
        float4 xb = *(const float4*)&sIn[swz(k, e0 + 4)];
        ulonglong2 wa = *(const ulonglong2*)&sW[k * 64 + tx * 4];
        ulonglong2 wb = *(const ulonglong2*)&sW[k * 64 + 32 + tx * 4];
        float xs0 = xa.x, xs1 = xa.y, xs2 = xa.z, xs3 = xa.w;
        float xs4 = xb.x, xs5 = xb.y, xs6 = xb.z, xs7 = xb.w;
        u64 xd;
#define STEP(ee, xv) \
        xd = dup2(xv); \
        acc[ee][0] = fma2(xd, wa.x, acc[ee][0]); \
        acc[ee][1] = fma2(xd, wa.y, acc[ee][1]); \
        acc[ee][2] = fma2(xd, wb.x, acc[ee][2]); \
        acc[ee][3] = fma2(xd, wb.y, acc[ee][3]);
        STEP(0, xs0) STEP(1, xs1) STEP(2, xs2) STEP(3, xs3)
        STEP(4, xs4) STEP(5, xs5) STEP(6, xs6) STEP(7, xs7)
#undef STEP
    }
}

__device__ __forceinline__ void init_acc8(u64 acc[8][4], const float* bias, int j0) {
    u64 bz[4];
#pragma unroll
    for (int jj = 0; jj < 4; jj++)
        bz[jj] = pk2(bias[j0 + 2 * jj], bias[j0 + 2 * jj + 1]);
#pragma unroll
    for (int ee = 0; ee < 8; ee++)
#pragma unroll
        for (int jj = 0; jj < 4; jj++) acc[ee][jj] = bz[jj];
}

__device__ __forceinline__ void unpack8(const u64 a[8][4], float tv[8][8], bool dorelu) {
#pragma unroll
    for (int ee = 0; ee < 8; ++ee)
#pragma unroll
        for (int jj = 0; jj < 4; ++jj) {
            float lo, hi;
            up2(a[ee][jj], lo, hi);
            if (dorelu) { lo = fmaxf(lo, 0.f); hi = fmaxf(hi, 0.f); }
            tv[ee][2 * jj] = lo;
            tv[ee][2 * jj + 1] = hi;
        }
}

// transposed (out-major, swizzled) store of an 8x8 thread tile
__device__ __forceinline__ void store_tile_T8(float* sOut, const float tv[8][8],
                                              int e0, int j0) {
#pragma unroll
    for (int jd = 0; jd < 8; ++jd) {
        int j = j0 + jd;
        *(float4*)&sOut[swz(j, e0)] =
            make_float4(tv[0][jd], tv[1][jd], tv[2][jd], tv[3][jd]);
        *(float4*)&sOut[swz(j, e0 + 4)] =
            make_float4(tv[4][jd], tv[5][jd], tv[6][jd], tv[7][jd]);
    }
}

// ------------------------- small kernels --------------------------------------
__global__ void zero_kernel() {
    int i = blockIdx.x * blockDim.x + threadIdx.x;
    if (i < NNODES * EMB / 4) {
        ((float4*)g_s0)[i] = make_float4(0.f, 0.f, 0.f, 0.f);
        ((float4*)g_s1)[i] = make_float4(0.f, 0.f, 0.f, 0.f);
    }
    if (i < NNODES) g_cnt[i] = 0.f;
    if (i < EMB) g_hg[i] = 0.f;
}

__global__ void prep_kernel(const float* __restrict__ W2, const float* __restrict__ b2,
                            const float* __restrict__ We1, const float* __restrict__ be1) {
    int idx = blockIdx.x * blockDim.x + threadIdx.x;
    if (idx < 2 * EMB * EMB) {
        int l = idx / (EMB * EMB);
        int r = idx % (EMB * EMB);
        int k = r / EMB, j = r % EMB;
        float a = 0.f;
        for (int i = 0; i < EMB; i++)
            a += W2[k * EMB + i] * We1[l * EMB * EMB + i * EMB + j];
        g_Wc[l][r] = a;
    } else if (idx < 2 * EMB * EMB + 2 * EMB) {
        int t2 = idx - 2 * EMB * EMB;
        int l = t2 / EMB, j = t2 % EMB;
        float a = be1[l * EMB + j];
        for (int i = 0; i < EMB; i++)
            a += b2[i] * We1[l * EMB * EMB + i * EMB + j];
        g_bc[l][j] = a;
    }
}

// ------------------------- edge kernel ----------------------------------------
// smem floats: sX 4096 | sT 8192 | sW1 2048 | sWc0 4096 | sWc1 4096 |
//              sB1 64 | sBc 128 | sDst 128
#define EDGE_SMEM_FLOATS (4096 + 8192 + 2048 + 4096 + 4096 + 64 + 128 + 128)

__global__ void __launch_bounds__(128, 2) edge_kernel(
    const float* __restrict__ obs, const int* __restrict__ dst,
    const float* __restrict__ W1, const float* __restrict__ b1, int E) {
    extern __shared__ float sm[];
    float* sX = sm;
    float* sT = sX + 4096;
    float* sW1 = sT + 8192;
    float* sWc0 = sW1 + 2048;
    float* sWc1 = sWc0 + 4096;
    float* sB1 = sWc1 + 4096;
    float* sBc = sB1 + 64;
    int* sDst = (int*)(sBc + 128);

    int t = threadIdx.x;
    int base = blockIdx.x * 128;

    load_w_reordered(sW1, W1, INDIM * EMB, t, 128);
    load_w_reordered(sWc0, &g_Wc[0][0], EMB * EMB, t, 128);
    load_w_reordered(sWc1, &g_Wc[1][0], EMB * EMB, t, 128);
    if (t < 64) sB1[t] = b1[t];
    sBc[t] = (&g_bc[0][0])[t];
    {
        int e = base + t;
        sDst[t] = (e < E) ? dst[e] : -1;
    }
    // obs tile, transposed into swizzled sX: 128 edges x 32
#pragma unroll
    for (int it = 0; it < 8; ++it) {
        int idx = t + 128 * it;       // 0..1023
        int e = idx >> 3;             // 0..127
        int q = idx & 7;              // float4 within row of 32
        int ge = base + e;
        float4 v = (ge < E) ? ((const float4*)obs)[(size_t)ge * 8 + q]
                            : make_float4(0.f, 0.f, 0.f, 0.f);
        sX[swz(q * 4 + 0, e)] = v.x;
        sX[swz(q * 4 + 1, e)] = v.y;
        sX[swz(q * 4 + 2, e)] = v.z;
        sX[swz(q * 4 + 3, e)] = v.w;
    }
    __syncthreads();

    int tx = t & 7, te = t >> 3;     // te 0..15
    int e0 = te * 8, j0 = tx * 8;

    // ---- GEMM1: t1 = relu(X @ W1 + b1) ----
    {
        u64 acc[8][4];
        init_acc8(acc, sB1, j0);
        gemm_tile8<INDIM, INDIM>(sX, sW1, acc, e0, tx);
        float tv[8][8];
        unpack8(acc, tv, true);
        store_tile_T8(sT, tv, e0, j0);
    }
    __syncthreads();

    // ---- GEMM2 per layer, then scatter ----
#pragma unroll 1
    for (int s = 0; s < 2; s++) {
        const float* sW = s ? sWc1 : sWc0;
        float* gS = s ? g_s1 : g_s0;
        u64 a[8][4];
        init_acc8(a, sBc + s * 64, j0);
        gemm_tile8<EMB, 16>(sT, sW, a, e0, tx);
        float tv[8][8];
        unpack8(a, tv, true);
#pragma unroll
        for (int ee = 0; ee < 8; ee++) {
            int d = sDst[e0 + ee];
            if (d >= 0) {
                float* p = gS + (size_t)d * 64 + j0;
                red4(p, tv[ee][0], tv[ee][1], tv[ee][2], tv[ee][3]);
                red4(p + 4, tv[ee][4], tv[ee][5], tv[ee][6], tv[ee][7]);
            }
        }
    }
    if (tx == 0) {
#pragma unroll
        for (int ee = 0; ee < 8; ee++) {
            int d = sDst[e0 + ee];
            if (d >= 0) red1(&g_cnt[d], 1.f);
        }
    }
}

// ------------------------- fused node kernel ----------------------------------
// smem floats: sA 8192 | sB 8192 | sW 4096 | sBias 192 | sCnt 128
#define NODE_SMEM_FLOATS (8192 + 8192 + 4096 + 192 + 128)

__global__ void __launch_bounds__(128, 2) node_kernel(
    const float* __restrict__ We2l, const float* __restrict__ be2l,
    const float* __restrict__ Wn3l, const float* __restrict__ bn3l,
    const float* __restrict__ Wn4l, const float* __restrict__ bn4l, int layer) {
    extern __shared__ float sm[];
    float* sA = sm;
    float* sB = sA + 8192;
    float* sW = sB + 8192;
    float* sBias = sW + 4096;
    float* sCnt = sBias + 192;

    int t = threadIdx.x;
    int base = blockIdx.x * 128;
    const float* gS = (layer == 0) ? g_s0 : g_s1;

    // load s-tile transposed into swizzled sA: 128 nodes x 64
#pragma unroll
    for (int it = 0; it < 16; ++it) {
        int idx = t + 128 * it;      // 0..2047
        int v = idx & 127;
        int q = idx >> 7;            // 0..15
        int gv = base + v;
        float4 x = (gv < NNODES) ? ((const float4*)gS)[(size_t)gv * 16 + q]
                                 : make_float4(0.f, 0.f, 0.f, 0.f);
        sA[swz(q * 4 + 0, v)] = x.x;
        sA[swz(q * 4 + 1, v)] = x.y;
        sA[swz(q * 4 + 2, v)] = x.z;
        sA[swz(q * 4 + 3, v)] = x.w;
    }
    {
        int gv = base + t;
        sCnt[t] = (gv < NNODES) ? g_cnt[gv] : 0.f;
    }
    if (t < 64) {
        sBias[t] = be2l[t];
        sBias[64 + t] = bn3l[t];
        sBias[128 + t] = bn4l[t];
    }
    load_w_reordered(sW, We2l, EMB * EMB, t, 128);
    __syncthreads();

    int tx = t & 7, te = t >> 3;
    int e0 = te * 8, j0 = tx * 8;

    // ---- stage A: agg = s @ We2 + cnt*be2 (then *h for layer 1) ----
    u64 a[8][4];
    {
        u64 bp[4];
#pragma unroll
        for (int jj = 0; jj < 4; jj++)
            bp[jj] = pk2(sBias[j0 + 2 * jj], sBias[j0 + 2 * jj + 1]);
#pragma unroll
        for (int ee = 0; ee < 8; ee++) {
            u64 c = dup2(sCnt[e0 + ee]);
#pragma unroll
            for (int jj = 0; jj < 4; jj++) a[ee][jj] = mul2(c, bp[jj]);
        }
    }
    gemm_tile8<EMB, 16>(sA, sW, a, e0, tx);
    __syncthreads();  // sA & sW reads done

    {
        float tv[8][8];
        unpack8(a, tv, false);
        if (layer == 1) {
#pragma unroll
            for (int ee = 0; ee < 8; ee++) {
                int gv = base + e0 + ee;
                if (gv < NNODES) {
                    float4 h1 = ((const float4*)g_h)[(size_t)gv * 16 + (j0 >> 2)];
                    float4 h2 = ((const float4*)g_h)[(size_t)gv * 16 + (j0 >> 2) + 1];
                    tv[ee][0] *= h1.x; tv[ee][1] *= h1.y;
                    tv[ee][2] *= h1.z; tv[ee][3] *= h1.w;
                    tv[ee][4] *= h2.x; tv[ee][5] *= h2.y;
                    tv[ee][6] *= h2.z; tv[ee][7] *= h2.w;
                }
            }
        }
        store_tile_T8(sB, tv, e0, j0);
    }
    load_w_reordered(sW, Wn3l, EMB * EMB, t, 128);
    __syncthreads();

    // ---- stage B: tB = relu(agg @ Wn3 + bn3) ----
    u64 b[8][4];
    init_acc8(b, sBias + 64, j0);
    gemm_tile8<EMB, 16>(sB, sW, b, e0, tx);
    __syncthreads();
    {
        float tv[8][8];
        unpack8(b, tv, true);
        store_tile_T8(sA, tv, e0, j0);
    }
    load_w_reordered(sW, Wn4l, EMB * EMB, t, 128);
    __syncthreads();

    // ---- stage C: hn = relu(tB @ Wn4 + bn4) ----
    u64 c[8][4];
    init_acc8(c, sBias + 128, j0);
    gemm_tile8<EMB, 16>(sA, sW, c, e0, tx);
    float hv[8][8];
    unpack8(c, hv, true);

    if (layer == 0) {
#pragma unroll
        for (int ee = 0; ee < 8; ee++) {
            int gv = base + e0 + ee;
            if (gv < NNODES) {
                float4* d4 = (float4*)(g_h + (size_t)gv * 64 + j0);
                d4[0] = make_float4(hv[ee][0], hv[ee][1], hv[ee][2], hv[ee][3]);
                d4[1] = make_float4(hv[ee][4], hv[ee][5], hv[ee][6], hv[ee][7]);
            }
        }
    } else {
        float p[8];
#pragma unroll
        for (int jd = 0; jd < 8; jd++) p[jd] = 0.f;
#pragma unroll
        for (int ee = 0; ee < 8; ee++) {
            int gv = base + e0 + ee;
            if (gv < NNODES) {
#pragma unroll
                for (int jd = 0; jd < 8; jd++) p[jd] += hv[ee][jd];
            }
        }
        // sB free (last read two syncs ago); use as reduction scratch [16][64]
        float* sRed = sB;
        *(float4*)&sRed[te * 64 + j0] = make_float4(p[0], p[1], p[2], p[3]);
        *(float4*)&sRed[te * 64 + j0 + 4] = make_float4(p[4], p[5], p[6], p[7]);
        __syncthreads();
        if (t < 64) {
            float s = 0.f;
#pragma unroll
            for (int r = 0; r < 16; r++) s += sRed[r * 64 + t];
            red1(&g_hg[t], s);
        }
    }
}

// ------------------------- readout --------------------------------------------
__global__ void final_kernel(const float* __restrict__ W3, const float* __restrict__ b3,
                             const float* __restrict__ W4, const float* __restrict__ b4,
                             float* __restrict__ out) {
    __shared__ float sh[EMB];
    int j = threadIdx.x;  // 64 threads
    float a = b3[j];
#pragma unroll
    for (int k = 0; k < EMB; k++) a += g_hg[k] * W3[k * EMB + j];
    sh[j] = fmaxf(a, 0.f);
    __syncthreads();
    if (j < NACT) {
        float o = b4[j];
#pragma unroll
        for (int k = 0; k < EMB; k++) o += sh[k] * W4[k * NACT + j];
        out[j] = o;
    }
}

// ------------------------- launch ---------------------------------------------
extern "C" void kernel_launch(void* const* d_in, const int* in_sizes, int n_in,
                              void* d_out, int out_size) {
    const float* edge_obs = (const float*)d_in[0];
    const int* dst = (const int*)d_in[1];
    int o = (n_in >= 19 && in_sizes[2] == 1) ? 3 : 2;
    const float* W1  = (const float*)d_in[o + 0];
    const float* b1  = (const float*)d_in[o + 1];
    const float* W2  = (const float*)d_in[o + 2];
    const float* b2  = (const float*)d_in[o + 3];
    const float* We1 = (const float*)d_in[o + 4];
    const float* be1 = (const float*)d_in[o + 5];
    const float* We2 = (const float*)d_in[o + 6];
    const float* be2 = (const float*)d_in[o + 7];
    const float* Wn3 = (const float*)d_in[o + 8];
    const float* bn3 = (const float*)d_in[o + 9];
    const float* Wn4 = (const float*)d_in[o + 10];
    const float* bn4 = (const float*)d_in[o + 11];
    const float* W3  = (const float*)d_in[o + 12];
    const float* b3  = (const float*)d_in[o + 13];
    const float* W4  = (const float*)d_in[o + 14];
    const float* b4  = (const float*)d_in[o + 15];
    float* out = (float*)d_out;
    int E = in_sizes[0] / INDIM;

    cudaFuncSetAttribute(edge_kernel, cudaFuncAttributeMaxDynamicSharedMemorySize,
                         EDGE_SMEM_FLOATS * 4);
    cudaFuncSetAttribute(node_kernel, cudaFuncAttributeMaxDynamicSharedMemorySize,
                         NODE_SMEM_FLOATS * 4);

    zero_kernel<<<(NNODES * EMB / 4 + 255) / 256, 256>>>();
    prep_kernel<<<(2 * EMB * EMB + 2 * EMB + 127) / 128, 128>>>(W2, b2, We1, be1);
    edge_kernel<<<(E + 127) / 128, 128, EDGE_SMEM_FLOATS * 4>>>(edge_obs, dst, W1, b1, E);
    for (int l = 0; l < 2; l++) {
        node_kernel<<<(NNODES + 127) / 128, 128, NODE_SMEM_FLOATS * 4>>>(
            We2 + l * EMB * EMB, be2 + l * EMB,
            Wn3 + l * EMB * EMB, bn3 + l * EMB,
            Wn4 + l * EMB * EMB, bn4 + l * EMB, l);
    }
    final_kernel<<<1, EMB>>>(W3, b3, W4, b4, out);
}